// round 14
// baseline (speedup 1.0000x reference)
#include <cuda_runtime.h>
#include <cuda_bf16.h>

// ---------------------------------------------------------------------------
// AliasFreeActivation: bias -> up2x(12x12 FIR, pad10, gain4) -> lrelu*sqrt2,
// clamp(+-256) -> 12x12 FIR down2x.
// Input [8,128,128,128] f32 -> mid [264,264] -> out [8,128,127,127] f32.
//
// Block = 32x64 output tile, 384 threads. Filters in __constant__ (uniform
// port). Input stored twice (sA, sB=shift-1); phase-B operand loads are
// LDS.128 (conflict-free: 21-quad row stride). Phase B computes an
// (even,odd) mid-row PAIR per job (7 shared input rows loaded once); stores
// are STS.128 (74-u64 mid row stride, quad-aligned). Mid parity-split into
// even/odd half-arrays. Phase C: balanced row groups {6,6,5,5,5,5} with
// compile-time trip counts. All FMAs are packed fma.rn.f32x2.
// ---------------------------------------------------------------------------

#define H      128
#define W      128
#define OHW    127
#define TY     32
#define TX     64
#define MSTR2  74          // half-mid row stride in (E,O) u64 pairs (quad 37)
#define INH    43
#define INW    84          // mult of 4 -> 16B rows; quad stride 21 == 5 mod 8
#define NTHREADS 384

#define S_SA_OFF    0
#define S_SB_OFF    (INH*INW)                   // 3612
#define S_MIDE_OFF  (2*INH*INW)                 // 7224  (byte 28896, 16B ok)
#define S_MIDO_OFF  (S_MIDE_OFF + 37*MSTR2*2)   // 7224+5476 = 12700 (16B ok)
#define SMEM_FLOATS (S_MIDO_OFF + 37*MSTR2*2)   // 18176 -> 72704 B

typedef unsigned long long u64;

__constant__ __align__(16) float c_fu[144];
__constant__ __align__(16) float c_fd[144];

__device__ __forceinline__ u64 ffma2(u64 a, u64 b, u64 c) {
    u64 d;
    asm("fma.rn.f32x2 %0, %1, %2, %3;" : "=l"(d) : "l"(a), "l"(b), "l"(c));
    return d;
}
__device__ __forceinline__ float2 unpack2(u64 d) {
    float2 f;
    asm("mov.b64 {%0, %1}, %2;" : "=f"(f.x), "=f"(f.y) : "l"(d));
    return f;
}

// Phase C worker: NR output rows, NM = 2*NR+10 mid rows. Compile-time trip
// counts -> full unroll, static rlo/rhi/ky folding, pipelinable loads.
template <int NR, int NM>
__device__ __forceinline__ void phase_c_group(const u64* __restrict__ hb,
                                              const u64* __restrict__ ob,
                                              u64* __restrict__ acc)
{
    #pragma unroll
    for (int r = 0; r < NR; r++) acc[r] = 0ull;

    #pragma unroll
    for (int mm = 0; mm < NM; mm++) {
        const u64* mrow = ((mm & 1) ? ob : hb) + (mm >> 1) * MSTR2;
        u64 md[6];
        #pragma unroll
        for (int s = 0; s < 6; s++) md[s] = mrow[s];

        const int rlo = (mm >= 12) ? ((mm - 10) >> 1) : 0;
        const int rhi = (mm >> 1) < (NR - 1) ? (mm >> 1) : (NR - 1);
        #pragma unroll
        for (int r = 0; r < NR; r++) {
            if (r < rlo || r > rhi) continue;       // folds at compile time
            const int ky = mm - 2 * r;              // compile-time constant
            const ulonglong2* fq = (const ulonglong2*)(c_fd + ky * 12);
            ulonglong2 f01 = fq[0], f23 = fq[1], f45 = fq[2];
            acc[r] = ffma2(md[0], f01.x, acc[r]);
            acc[r] = ffma2(md[1], f01.y, acc[r]);
            acc[r] = ffma2(md[2], f23.x, acc[r]);
            acc[r] = ffma2(md[3], f23.y, acc[r]);
            acc[r] = ffma2(md[4], f45.x, acc[r]);
            acc[r] = ffma2(md[5], f45.y, acc[r]);
        }
    }
}

__global__ __launch_bounds__(NTHREADS, 2)
void afa_fused_kernel(const float* __restrict__ in,
                      const float* __restrict__ bias,
                      float* __restrict__ out)
{
    extern __shared__ float sm[];
    float* s_sa   = sm + S_SA_OFF;
    float* s_sb   = sm + S_SB_OFF;
    u64*   s_midE = (u64*)(sm + S_MIDE_OFF);   // even mid rows, (E,O) pairs
    u64*   s_midO = (u64*)(sm + S_MIDO_OFF);   // odd  mid rows

    const int tid   = threadIdx.x;
    const int b     = blockIdx.x;
    const int plane = b >> 3;
    const int t8    = b & 7;
    const int oy0   = (t8 >> 1) * TY;
    const int ox0   = (t8 & 1) * TX;
    const int iy0   = oy0 - 5;
    const int ix0   = ox0 - 5;

    const float bv = __ldg(&bias[plane & 127]);
    const float* __restrict__ inp = in + (size_t)plane * (H * W);

    // ---- Phase A: dual input copies (+bias, zero pad OOB) ------------------
    for (int i = tid; i < INH * INW; i += NTHREADS) {
        const int r  = i / INW;
        const int cc = i - r * INW;
        const int gy = iy0 + r;
        const int gx = ix0 + cc;
        float v = 0.0f;
        if ((unsigned)gy < (unsigned)H && (unsigned)gx < (unsigned)W && cc < 78)
            v = __ldg(&inp[gy * W + gx]) + bv;
        s_sa[i] = v;                       // sA[w] = x[w]
        if (cc > 0) s_sb[i - 1] = v;       // sB[w] = x[w+1]
    }
    __syncthreads();

    // ---- Phase B: row-PAIR polyphase up-conv + activation ------------------
    // Job tid<333: mid rows (2q, 2q+1), 16 columns (8 E/O pairs).
    // Shared input rows q..q+6 loaded once (LDS.128); even row uses fu row 2t
    // (t<6), odd row uses fu row 2t-1 (t>=1). Filter offsets compile-time.
    // Gain 4 folded into activation gain G.
    const float G = 5.65685424949238019f;   // 4*sqrt(2)
    if (tid < 333) {
        const int chunk = tid / 37;           // 0..8
        const int q     = tid - chunk * 37;   // 0..36
        const int j0    = chunk * 8;          // pair/word column base (even)

        u64 ae[8], ao[8];
        #pragma unroll
        for (int jj = 0; jj < 8; jj++) { ae[jj] = 0ull; ao[jj] = 0ull; }

        #pragma unroll
        for (int t = 0; t < 7; t++) {
            const int rowoff = (q + t) * INW + j0;         // 16B aligned
            const ulonglong2* pa = (const ulonglong2*)(s_sa + rowoff);
            const ulonglong2* pb = (const ulonglong2*)(s_sb + rowoff);
            u64 pe[7], po[6];
            {
                ulonglong2 v0 = pa[0], v1 = pa[1], v2 = pa[2], v3 = pa[3];
                pe[0] = v0.x; pe[1] = v0.y; pe[2] = v1.x; pe[3] = v1.y;
                pe[4] = v2.x; pe[5] = v2.y; pe[6] = v3.x; (void)v3.y;
            }
            {
                ulonglong2 w0 = pb[0], w1 = pb[1], w2 = pb[2];
                po[0] = w0.x; po[1] = w0.y; po[2] = w1.x;
                po[3] = w1.y; po[4] = w2.x; po[5] = w2.y;
            }

            #define PR(a) (((a) & 1) ? po[(a) >> 1] : pe[(a) >> 1])
            if (t < 6) {   // even mid row, filter row 2t (compile-time)
                const ulonglong2* fq = (const ulonglong2*)(c_fu + (2 * t) * 12);
                ulonglong2 f01 = fq[0], f23 = fq[1], f45 = fq[2];
                #pragma unroll
                for (int jj = 0; jj < 8; jj++) {
                    ae[jj] = ffma2(PR(jj + 0), f01.x, ae[jj]);
                    ae[jj] = ffma2(PR(jj + 1), f01.y, ae[jj]);
                    ae[jj] = ffma2(PR(jj + 2), f23.x, ae[jj]);
                    ae[jj] = ffma2(PR(jj + 3), f23.y, ae[jj]);
                    ae[jj] = ffma2(PR(jj + 4), f45.x, ae[jj]);
                    ae[jj] = ffma2(PR(jj + 5), f45.y, ae[jj]);
                }
            }
            if (t >= 1) {  // odd mid row, filter row 2t-1 (compile-time)
                const ulonglong2* fq = (const ulonglong2*)(c_fu + (2 * t - 1) * 12);
                ulonglong2 f01 = fq[0], f23 = fq[1], f45 = fq[2];
                #pragma unroll
                for (int jj = 0; jj < 8; jj++) {
                    ao[jj] = ffma2(PR(jj + 0), f01.x, ao[jj]);
                    ao[jj] = ffma2(PR(jj + 1), f01.y, ao[jj]);
                    ao[jj] = ffma2(PR(jj + 2), f23.x, ao[jj]);
                    ao[jj] = ffma2(PR(jj + 3), f23.y, ao[jj]);
                    ao[jj] = ffma2(PR(jj + 4), f45.x, ao[jj]);
                    ao[jj] = ffma2(PR(jj + 5), f45.y, ao[jj]);
                }
            }
            #undef PR
        }
        // activation (gain folded) + STS.128 stores (quad-aligned, stride 37)
        float4* re = (float4*)(s_midE + q * MSTR2 + j0);
        float4* ro = (float4*)(s_midO + q * MSTR2 + j0);
        #pragma unroll
        for (int k = 0; k < 4; k++) {
            float2 v0 = unpack2(ae[2 * k]);
            float2 v1 = unpack2(ae[2 * k + 1]);
            float4 ve;
            ve.x = fminf(fmaxf(fmaxf(v0.x, 0.2f * v0.x) * G, -256.0f), 256.0f);
            ve.y = fminf(fmaxf(fmaxf(v0.y, 0.2f * v0.y) * G, -256.0f), 256.0f);
            ve.z = fminf(fmaxf(fmaxf(v1.x, 0.2f * v1.x) * G, -256.0f), 256.0f);
            ve.w = fminf(fmaxf(fmaxf(v1.y, 0.2f * v1.y) * G, -256.0f), 256.0f);
            re[k] = ve;
            float2 w0 = unpack2(ao[2 * k]);
            float2 w1 = unpack2(ao[2 * k + 1]);
            float4 vo;
            vo.x = fminf(fmaxf(fmaxf(w0.x, 0.2f * w0.x) * G, -256.0f), 256.0f);
            vo.y = fminf(fmaxf(fmaxf(w0.y, 0.2f * w0.y) * G, -256.0f), 256.0f);
            vo.z = fminf(fmaxf(fmaxf(w1.x, 0.2f * w1.x) * G, -256.0f), 256.0f);
            vo.w = fminf(fmaxf(fmaxf(w1.y, 0.2f * w1.y) * G, -256.0f), 256.0f);
            ro[k] = vo;
        }
    }
    __syncthreads();

    // ---- Phase C: 12x12 down-conv stride 2, packed over (E,O) --------------
    // 12 warps = 6 balanced row groups {6,6,5,5,5,5} x 2 col halves.
    // lane = column. Compile-time trip counts (no dynamic breaks).
    {
        const int wrp  = tid >> 5;
        const int lane = tid & 31;
        const int rg   = wrp >> 1;                  // 0..5
        const int c    = ((wrp & 1) << 5) + lane;   // 0..63
        const int r0   = (rg < 2) ? 6 * rg : 12 + 5 * (rg - 2);
        const u64* hb  = s_midE + r0 * MSTR2 + c;
        const u64* ob  = s_midO + r0 * MSTR2 + c;

        const int gx = ox0 + c;
        float* op = out + (size_t)plane * (OHW * OHW) + gx;

        if (rg < 2) {
            u64 acc[6];
            phase_c_group<6, 22>(hb, ob, acc);
            if (gx < OHW) {
                #pragma unroll
                for (int r = 0; r < 6; r++) {
                    const int gy = oy0 + r0 + r;
                    if (gy < OHW) {
                        float2 v = unpack2(acc[r]);
                        op[gy * OHW] = v.x + v.y;
                    }
                }
            }
        } else {
            u64 acc[5];
            phase_c_group<5, 20>(hb, ob, acc);
            if (gx < OHW) {
                #pragma unroll
                for (int r = 0; r < 5; r++) {
                    const int gy = oy0 + r0 + r;
                    if (gy < OHW) {
                        float2 v = unpack2(acc[r]);
                        op[gy * OHW] = v.x + v.y;
                    }
                }
            }
        }
    }
}

extern "C" void kernel_launch(void* const* d_in, const int* in_sizes, int n_in,
                              void* d_out, int out_size)
{
    const float* in   = (const float*)d_in[0];
    const float* bias = (const float*)d_in[1];
    const float* fu   = (const float*)d_in[2];
    const float* fd   = (const float*)d_in[3];
    float* out        = (float*)d_out;

    // Filters into constant memory (async D2D copies: graph-capturable).
    cudaMemcpyToSymbolAsync(c_fu, fu, 144 * sizeof(float), 0,
                            cudaMemcpyDeviceToDevice, 0);
    cudaMemcpyToSymbolAsync(c_fd, fd, 144 * sizeof(float), 0,
                            cudaMemcpyDeviceToDevice, 0);

    const size_t smem = SMEM_FLOATS * sizeof(float);   // 72704 B
    cudaFuncSetAttribute(afa_fused_kernel,
                         cudaFuncAttributeMaxDynamicSharedMemorySize, (int)smem);

    const int nblocks = 1024 * 8;
    afa_fused_kernel<<<nblocks, NTHREADS, smem>>>(in, bias, out);
}